// round 7
// baseline (speedup 1.0000x reference)
#include <cuda_runtime.h>
#include <math.h>

typedef unsigned long long u64;
typedef unsigned int u32;

#define BI 8
#define PP 2000
#define NC 81
#define CPP 80
#define CAP 16384
#define KPRE 2048
#define DET 100
#define NBIN 8192
#define BINSHIFT 50   // key>>50 == float bits [31:18]; sign==0 for scores>0
#define BCAP 8192
#define GENBLK 64     // gen blocks per image, 32 proposals each (2048 >= 2000)
#define W_IMGF 1333.0f
#define H_IMGF 800.0f
#define SCORE_T 0.05f
#define NMS_T 0.5f
#define XFORM_CLIP 4.135166556742356f

// ---------------- device scratch (zero-initialized at load) ----------------
__device__ int g_cnt[BI];
__device__ u64 g_keys[BI][CAP];          // candidates; [0,2048) reused for sorted keys
__device__ float4 g_boxes[BI][KPRE];
__device__ unsigned short g_clist[BI][KPRE];
__device__ int g_classoff[BI][CPP];
__device__ int g_classcnt[BI][CPP];
__device__ unsigned char g_keep[BI][KPRE];
__device__ int g_K[BI];
__device__ int g_done_gen[BI];
__device__ int g_done_nms[BI];

// ---------------- helpers ----------------
__device__ __forceinline__ float4 decode_clip(float4 pr, float4 rel) {
    float w = pr.z - pr.x;
    float h = pr.w - pr.y;
    float cx = pr.x + 0.5f * w;
    float cy = pr.y + 0.5f * h;
    float dx = rel.x / 10.0f;
    float dy = rel.y / 10.0f;
    float dw = fminf(rel.z / 5.0f, XFORM_CLIP);
    float dh = fminf(rel.w / 5.0f, XFORM_CLIP);
    float pcx = dx * w + cx;
    float pcy = dy * h + cy;
    float pw = expf(dw) * w;
    float ph = expf(dh) * h;
    float x1 = fminf(fmaxf(pcx - 0.5f * pw, 0.0f), W_IMGF);
    float y1 = fminf(fmaxf(pcy - 0.5f * ph, 0.0f), H_IMGF);
    float x2 = fminf(fmaxf(pcx + 0.5f * pw, 0.0f), W_IMGF);
    float y2 = fminf(fmaxf(pcy + 0.5f * ph, 0.0f), H_IMGF);
    return make_float4(x1, y1, x2, y2);
}

__device__ __forceinline__ u64 sel_mm(u64 v, u64 o, bool takeMax) {
    return takeMax ? (v > o ? v : o) : (v < o ? v : o);
}

// ================= K1: fused gen + select (last block per image) ==========
__global__ void __launch_bounds__(1024, 1)
k_gen_select(const float* __restrict__ logits,
             const float* __restrict__ boxreg,
             const float* __restrict__ props) {
    extern __shared__ char smc[];
    const int tid = threadIdx.x;
    const int lane = tid & 31;
    const int wid = tid >> 5;
    const int b = blockIdx.x >> 6;       // /GENBLK
    const int sub = blockIdx.x & 63;

    __shared__ int sdone, s_t, s_A, s_R, aCtr, bCtr, wsum[32];

    // ---------------- GEN phase: 32 proposals per block (1/warp) ----------
    int p = sub * 32 + wid;
    if (p < PP) {
        int gw = b * PP + p;
        const float* lrow = logits + (long long)gw * NC;
        float l0 = lrow[lane];
        float l1 = lrow[lane + 32];
        float l2 = (lane + 64 < NC) ? lrow[lane + 64] : -1e30f;

        float m = fmaxf(l0, fmaxf(l1, l2));
        #pragma unroll
        for (int o = 16; o; o >>= 1) m = fmaxf(m, __shfl_xor_sync(0xffffffffu, m, o));
        float e0 = __expf(l0 - m);
        float e1 = __expf(l1 - m);
        float e2 = (lane + 64 < NC) ? __expf(l2 - m) : 0.0f;
        float s = e0 + e1 + e2;
        #pragma unroll
        for (int o = 16; o; o >>= 1) s += __shfl_xor_sync(0xffffffffu, s, o);
        float thresh = SCORE_T * s;

        float4 pr = reinterpret_cast<const float4*>(props)[gw];

        bool ok[3];
        float sc[3];
        #pragma unroll
        for (int r = 0; r < 3; r++) {
            int ci = lane + r * 32;
            float e = (r == 0) ? e0 : ((r == 1) ? e1 : e2);
            ok[r] = false;
            sc[r] = 0.0f;
            if (ci >= 1 && ci < NC && e > thresh) {
                float4 rel = reinterpret_cast<const float4*>(boxreg)[(long long)gw * NC + ci];
                float4 bx = decode_clip(pr, rel);
                if ((bx.z - bx.x) >= 0.01f && (bx.w - bx.y) >= 0.01f) {
                    ok[r] = true;
                    sc[r] = e / s;
                }
            }
        }

        unsigned bal[3];
        bal[0] = __ballot_sync(0xffffffffu, ok[0]);
        bal[1] = __ballot_sync(0xffffffffu, ok[1]);
        bal[2] = __ballot_sync(0xffffffffu, ok[2]);
        int cnt0 = __popc(bal[0]);
        int cnt1 = __popc(bal[1]);
        int tot = cnt0 + cnt1 + __popc(bal[2]);
        int base = 0;
        if (lane == 0 && tot) base = atomicAdd(&g_cnt[b], tot);
        base = __shfl_sync(0xffffffffu, base, 0);

        unsigned below = (1u << lane) - 1u;
        #pragma unroll
        for (int r = 0; r < 3; r++) {
            if (ok[r]) {
                int off = __popc(bal[r] & below) + ((r > 0) ? cnt0 : 0) + ((r > 1) ? cnt1 : 0);
                int slot = base + off;
                if (slot < CAP) {
                    unsigned idx = (unsigned)(p * CPP + (lane + r * 32 - 1));
                    g_keys[b][slot] = ((u64)__float_as_uint(sc[r]) << 32) |
                                      (u64)(0xFFFFFFFFu - idx);
                }
            }
        }
    }

    // ---------------- handoff: last block of this image continues --------
    __threadfence();
    __syncthreads();
    if (tid == 0) sdone = atomicAdd(&g_done_gen[b], 1);
    __syncthreads();
    if (sdone != GENBLK - 1) return;
    if (tid == 0) g_done_gen[b] = 0;
    __threadfence();

    // ---------------- SELECT phase ----------------
    u64* keys = (u64*)smc;                               // 2048 u64
    char* reg2 = smc + 16384;
    int* hist = (int*)reg2;                              // 8192 int (32KB)
    u64* bound = (u64*)reg2;                             // 8192 u64 (64KB)
    unsigned short* chcnt = (unsigned short*)reg2;       // 64*80 u16
    int* classoff = (int*)(reg2 + 10240);
    int* classcnt = classoff + CPP;

    const int cnt = min(g_cnt[b], CAP);
    const int K = min(cnt, KPRE);

    // A1: histogram on float bits [30:18]
    for (int i = tid; i < NBIN; i += 1024) hist[i] = 0;
    if (tid == 0) { s_t = 0x7FFFFFFF; s_A = 0; s_R = 0; aCtr = 0; bCtr = 0; }
    __syncthreads();
    for (int base = 0; base < cnt; base += 1024) {
        int i = base + tid;
        int bin = (i < cnt) ? (int)(g_keys[b][i] >> BINSHIFT) : -1;
        unsigned mask = __match_any_sync(0xffffffffu, bin);
        if (bin >= 0 && lane == (__ffs(mask) - 1))
            atomicAdd(&hist[bin], __popc(mask));
    }
    __syncthreads();

    // A2: descending scan, find rank-K crossing bin
    {
        const int BPT = NBIN / 1024;
        int localsum = 0;
        int bhi = NBIN - 1 - BPT * tid;
        #pragma unroll
        for (int j = 0; j < BPT; j++) localsum += hist[bhi - j];
        int v = localsum;
        #pragma unroll
        for (int o = 1; o < 32; o <<= 1) {
            int n = __shfl_up_sync(0xffffffffu, v, o);
            if (lane >= o) v += n;
        }
        if (lane == 31) wsum[wid] = v;
        __syncthreads();
        if (wid == 0) {
            int w = wsum[lane];
            #pragma unroll
            for (int o = 1; o < 32; o <<= 1) {
                int n = __shfl_up_sync(0xffffffffu, w, o);
                if (lane >= o) w += n;
            }
            wsum[lane] = w;
        }
        __syncthreads();
        int incl = v + ((wid > 0) ? wsum[wid - 1] : 0);
        int excl = incl - localsum;
        if (K > 0 && excl < K && K <= incl) {
            int run = excl;
            for (int j = 0; j < BPT; j++) {
                int bin = bhi - j;
                int h = hist[bin];
                if (run < K && K <= run + h) { s_t = bin; s_A = run; s_R = K - run; }
                run += h;
            }
        }
    }
    __syncthreads();
    const int tbin = s_t, A = s_A, R = s_R;
    __syncthreads();  // hist dead; bound overlays it

    // A3: compact above-bin keys to smem; gather boundary bin
    for (int base = 0; base < cnt; base += 1024) {
        int i = base + tid;
        u64 key = (i < cnt) ? g_keys[b][i] : 0ull;
        int bin = (i < cnt) ? (int)(key >> BINSHIFT) : -1;
        bool above = bin > tbin;
        bool atb = bin == tbin;
        unsigned balA = __ballot_sync(0xffffffffu, above);
        unsigned balB = __ballot_sync(0xffffffffu, atb);
        int bA = 0, bB = 0;
        if (lane == 0) {
            if (balA) bA = atomicAdd(&aCtr, __popc(balA));
            if (balB) bB = atomicAdd(&bCtr, __popc(balB));
        }
        bA = __shfl_sync(0xffffffffu, bA, 0);
        bB = __shfl_sync(0xffffffffu, bB, 0);
        unsigned below = (1u << lane) - 1u;
        if (above) keys[bA + __popc(balA & below)] = key;
        else if (atb) {
            int pos = bB + __popc(balB & below);
            if (pos < BCAP) bound[pos] = key;
        }
    }
    __syncthreads();

    // A4: boundary bin -> top R. Common case m<=64: single-warp register sort.
    int m = min(bCtr, BCAP);
    if (m > 0 && m <= 64) {
        if (wid == 0) {
            u64 r0 = (lane < m) ? bound[lane] : 0ull;
            u64 r1 = (lane + 32 < m) ? bound[lane + 32] : 0ull;
            #pragma unroll
            for (int k2 = 2; k2 <= 32; k2 <<= 1) {
                #pragma unroll
                for (int j = k2 >> 1; j; j >>= 1) {
                    {
                        u64 o = __shfl_xor_sync(0xffffffffu, r0, j);
                        r0 = sel_mm(r0, o, ((lane & k2) == 0) == ((lane & j) == 0));
                    }
                    {
                        int x = lane + 32;
                        u64 o = __shfl_xor_sync(0xffffffffu, r1, j);
                        r1 = sel_mm(r1, o, ((x & k2) == 0) == ((x & j) == 0));
                    }
                }
            }
            // k=64 merge, descending (up=true for all x<64)
            u64 hi = (r0 > r1) ? r0 : r1;
            u64 lo = (r0 > r1) ? r1 : r0;
            r0 = hi; r1 = lo;
            #pragma unroll
            for (int j = 16; j; j >>= 1) {
                bool tkm = ((lane & j) == 0);
                u64 o0 = __shfl_xor_sync(0xffffffffu, r0, j);
                u64 o1 = __shfl_xor_sync(0xffffffffu, r1, j);
                r0 = sel_mm(r0, o0, tkm);
                r1 = sel_mm(r1, o1, tkm);
            }
            if (lane < R) keys[A + lane] = r0;
            if (lane + 32 < R) keys[A + lane + 32] = r1;
        }
    } else if (m > 64) {
        int M = 1;
        while (M < m) M <<= 1;
        for (int i = m + tid; i < M; i += 1024) bound[i] = 0ull;
        __syncthreads();
        for (int k2 = 2; k2 <= M; k2 <<= 1) {
            for (int j = k2 >> 1; j; j >>= 1) {
                for (int i = tid; i < M; i += 1024) {
                    int ixj = i ^ j;
                    if (ixj > i) {
                        u64 a = bound[i], c = bound[ixj];
                        bool up = ((i & k2) == 0);
                        if ((a < c) == up) { bound[i] = c; bound[ixj] = a; }
                    }
                }
                __syncthreads();
            }
        }
        for (int i = tid; i < R; i += 1024) keys[A + i] = bound[i];
    }
    for (int i = K + tid; i < KPRE; i += 1024) keys[i] = 0ull;
    __syncthreads();

    // A5: descending bitonic sort of 2048 keys (register 64-blocks + smem merges)
    {
        int base = wid * 64;
        u64 r0 = keys[base + lane];
        u64 r1 = keys[base + lane + 32];
        #pragma unroll
        for (int k2 = 2; k2 <= 32; k2 <<= 1) {
            #pragma unroll
            for (int j = k2 >> 1; j; j >>= 1) {
                {
                    int x = lane;
                    u64 o = __shfl_xor_sync(0xffffffffu, r0, j);
                    r0 = sel_mm(r0, o, ((x & k2) == 0) == ((x & j) == 0));
                }
                {
                    int x = lane + 32;
                    u64 o = __shfl_xor_sync(0xffffffffu, r1, j);
                    r1 = sel_mm(r1, o, ((x & k2) == 0) == ((x & j) == 0));
                }
            }
        }
        {
            bool up = ((wid & 1) == 0);
            u64 lo = (r0 < r1) ? r0 : r1;
            u64 hi = (r0 < r1) ? r1 : r0;
            r0 = up ? hi : lo;
            r1 = up ? lo : hi;
            #pragma unroll
            for (int j = 16; j; j >>= 1) {
                bool tkm = up == ((lane & j) == 0);
                u64 o0 = __shfl_xor_sync(0xffffffffu, r0, j);
                u64 o1 = __shfl_xor_sync(0xffffffffu, r1, j);
                r0 = sel_mm(r0, o0, tkm);
                r1 = sel_mm(r1, o1, tkm);
            }
        }
        keys[base + lane] = r0;
        keys[base + lane + 32] = r1;
    }
    __syncthreads();
    for (int k2 = 128; k2 <= KPRE; k2 <<= 1) {
        for (int j = k2 >> 1; j >= 64; j >>= 1) {
            int i = ((tid & ~(j - 1)) << 1) | (tid & (j - 1));
            u64 a = keys[i], c = keys[i + j];
            bool up = ((i & k2) == 0);
            if ((a < c) == up) { keys[i] = c; keys[i + j] = a; }
            __syncthreads();
        }
        {
            int base = wid * 64;
            bool up = ((base & k2) == 0);
            u64 r0 = keys[base + lane];
            u64 r1 = keys[base + lane + 32];
            u64 lo = (r0 < r1) ? r0 : r1;
            u64 hi = (r0 < r1) ? r1 : r0;
            r0 = up ? hi : lo;
            r1 = up ? lo : hi;
            #pragma unroll
            for (int j = 16; j; j >>= 1) {
                bool tkm = up == ((lane & j) == 0);
                u64 o0 = __shfl_xor_sync(0xffffffffu, r0, j);
                u64 o1 = __shfl_xor_sync(0xffffffffu, r1, j);
                r0 = sel_mm(r0, o0, tkm);
                r1 = sel_mm(r1, o1, tkm);
            }
            keys[base + lane] = r0;
            keys[base + lane + 32] = r1;
        }
        __syncthreads();
    }

    // B1: store sorted keys (coalesced); no decode here
    for (int t = tid; t < KPRE; t += 1024) g_keys[b][t] = keys[t];
    for (int i = tid; i < 64 * CPP; i += 1024) chcnt[i] = 0;
    __syncthreads();

    // B2: stable counting sort by class -> g_clist
    for (int c = wid; c < 64; c += 32) {
        int t = c * 32 + lane;
        u64 key = keys[t];
        unsigned L = (t < K) ? ((0xFFFFFFFFu - (u32)key) % CPP) : 0xFFu;
        unsigned mask = __match_any_sync(0xffffffffu, L);
        if (L < CPP && lane == (__ffs(mask) - 1))
            chcnt[c * CPP + L] = (unsigned short)__popc(mask);
    }
    __syncthreads();
    if (tid < CPP) {
        int run = 0;
        for (int c = 0; c < 64; c++) {
            int v = chcnt[c * CPP + tid];
            chcnt[c * CPP + tid] = (unsigned short)run;
            run += v;
        }
        classcnt[tid] = run;
        g_classcnt[b][tid] = run;
    }
    __syncthreads();
    // exclusive scan over 80 class counts (3 warps)
    {
        int v = 0;
        if (tid < 96) {
            v = (tid < CPP) ? classcnt[tid] : 0;
            #pragma unroll
            for (int o = 1; o < 32; o <<= 1) {
                int n = __shfl_up_sync(0xffffffffu, v, o);
                if (lane >= o) v += n;
            }
            if (lane == 31) wsum[wid] = v;
        }
        __syncthreads();
        if (tid < CPP) {
            int add = 0;
            for (int w = 0; w < wid; w++) add += wsum[w];
            int off = v + add - classcnt[tid];
            classoff[tid] = off;
            g_classoff[b][tid] = off;
        }
    }
    __syncthreads();
    for (int c = wid; c < 64; c += 32) {
        int t = c * 32 + lane;
        u64 key = keys[t];
        unsigned L = (t < K) ? ((0xFFFFFFFFu - (u32)key) % CPP) : 0xFFu;
        unsigned mask = __match_any_sync(0xffffffffu, L);
        if (L < CPP) {
            int rank = __popc(mask & ((1u << lane) - 1u));
            g_clist[b][classoff[L] + chcnt[c * CPP + L] + rank] = (unsigned short)t;
        }
    }

    if (tid == 0) { g_K[b] = K; g_cnt[b] = 0; }
}

// ================= K2: per-class NMS (with decode) + fused output =========
__global__ void __launch_bounds__(128)
k_nms_out(const float* __restrict__ boxreg,
          const float* __restrict__ props,
          float* __restrict__ out) {
    __shared__ float4 sbox[KPRE];
    __shared__ float sarea[KPRE];
    __shared__ int sdone, sKeptTot, wscan[4];

    const int cls = blockIdx.x;
    const int b = blockIdx.y;
    const int tid = threadIdx.x;
    const int lane = tid & 31;
    const int wid = tid >> 5;
    const int n = g_classcnt[b][cls];

    if (n > 0) {
        const int off = g_classoff[b][cls];
        const unsigned short* list = &g_clist[b][off];
        // decode this class's boxes (parallel across 128 threads & 640 blocks)
        for (int e = tid; e < n; e += 128) {
            int t = list[e];
            u64 key = g_keys[b][t];
            u32 idx = 0xFFFFFFFFu - (u32)key;
            int p = idx / CPP;
            int cm1 = idx - p * CPP;
            int gw = b * PP + p;
            float4 pr = reinterpret_cast<const float4*>(props)[gw];
            float4 rel = reinterpret_cast<const float4*>(boxreg)[(long long)gw * NC + cm1 + 1];
            float4 bx = decode_clip(pr, rel);
            sbox[e] = bx;
            sarea[e] = fmaxf(bx.z - bx.x, 0.f) * fmaxf(bx.w - bx.y, 0.f);
            g_boxes[b][t] = bx;
        }
        __syncthreads();

        if (wid == 0) {
            u64 kept = ~0ull;
            for (int i = 0; i < n; i++) {
                int il = i & 31, is = i >> 5;
                unsigned ki = __shfl_sync(0xffffffffu, (unsigned)((kept >> is) & 1ull), il);
                if (!ki) continue;
                float4 bi = sbox[i];
                float ai = sarea[i];
                for (int ss = is; ss * 32 + lane < n; ss++) {
                    int e = ss * 32 + lane;
                    if (e > i && ((kept >> ss) & 1ull)) {
                        float4 be = sbox[e];
                        float lx = fmaxf(bi.x, be.x), ly = fmaxf(bi.y, be.y);
                        float rx = fminf(bi.z, be.z), ry = fminf(bi.w, be.w);
                        float iw = fmaxf(rx - lx, 0.f), ih = fmaxf(ry - ly, 0.f);
                        float inter = iw * ih;
                        float uni = ai + sarea[e] - inter;
                        if (inter / fmaxf(uni, 1e-9f) > NMS_T) kept &= ~(1ull << ss);
                    }
                }
            }
            for (int ss = 0; ss * 32 + lane < n; ss++) {
                int e = ss * 32 + lane;
                g_keep[b][list[e]] = (unsigned char)((kept >> ss) & 1ull);
            }
        }
    }

    // ---- last-block-done: 80th block for image b emits output ----
    __threadfence();
    __syncthreads();
    if (tid == 0) sdone = atomicAdd(&g_done_nms[b], 1);
    __syncthreads();
    if (sdone != CPP - 1) return;
    __threadfence();

    // stable compaction: kept (t asc) then non-kept (t asc); top-100 out.
    const int CH = KPRE / 128;  // 16 entries per thread
    int base = tid * CH;
    u64 f0 = *reinterpret_cast<const u64*>(&g_keep[b][base]);
    u64 f1 = *reinterpret_cast<const u64*>(&g_keep[b][base + 8]);
    int cnts = __popcll(f0 & 0x0101010101010101ull) +
               __popcll(f1 & 0x0101010101010101ull);
    int v = cnts;
    #pragma unroll
    for (int o = 1; o < 32; o <<= 1) {
        int t2 = __shfl_up_sync(0xffffffffu, v, o);
        if (lane >= o) v += t2;
    }
    if (lane == 31) wscan[wid] = v;
    __syncthreads();
    if (tid == 0) {
        int run = 0;
        #pragma unroll
        for (int w = 0; w < 4; w++) { int t2 = wscan[w]; wscan[w] = run; run += t2; }
        sKeptTot = run;
    }
    __syncthreads();
    int run = (v - cnts) + wscan[wid];
    int keptTotal = sKeptTot;
    #pragma unroll
    for (int j = 0; j < CH; j++) {
        int e = base + j;
        bool kp = (((j < 8) ? (f0 >> (8 * j)) : (f1 >> (8 * (j - 8)))) & 1ull) != 0;
        int slot;
        if (kp) { slot = run; run++; }
        else slot = keptTotal + (e - run);
        if (slot < DET) {
            u64 key = g_keys[b][e];
            float sc = kp ? __uint_as_float((u32)(key >> 32)) : -1.0f;
            u32 idx = 0xFFFFFFFFu - (u32)key;
            float4 bx = g_boxes[b][e];
            out[(b * DET + slot) * 4 + 0] = bx.x;
            out[(b * DET + slot) * 4 + 1] = bx.y;
            out[(b * DET + slot) * 4 + 2] = bx.z;
            out[(b * DET + slot) * 4 + 3] = bx.w;
            out[BI * DET * 4 + b * DET + slot] = sc;
            out[BI * DET * 5 + b * DET + slot] = (float)(idx % CPP + 1);
            out[BI * DET * 6 + b * DET + slot] = kp ? 1.0f : 0.0f;
        }
    }
    if (tid == 0) g_done_nms[b] = 0;  // reset for next replay
}

// ---------------- launch ----------------
extern "C" void kernel_launch(void* const* d_in, const int* in_sizes, int n_in,
                              void* d_out, int out_size) {
    const float* logits = (const float*)d_in[0];
    const float* boxreg = (const float*)d_in[1];
    const float* props  = (const float*)d_in[2];
    float* out = (float*)d_out;

    cudaFuncSetAttribute(k_gen_select, cudaFuncAttributeMaxDynamicSharedMemorySize, 147456);

    k_gen_select<<<BI * GENBLK, 1024, 147456>>>(logits, boxreg, props);
    k_nms_out<<<dim3(CPP, BI), 128>>>(boxreg, props, out);
}

// round 8
// speedup vs baseline: 1.2970x; 1.2970x over previous
#include <cuda_runtime.h>
#include <math.h>

typedef unsigned long long u64;
typedef unsigned int u32;

#define BI 8
#define PP 2000
#define NC 81
#define CPP 80
#define CAP 16384
#define KPRE 2048
#define DET 100
#define NBIN 8192
#define BINSHIFT 50   // key>>50 == float bits [31:18]; sign==0 for scores>0
#define BCAP 8192
#define MAXN 256      // fast-path cap on per-class candidate count
#define W_IMGF 1333.0f
#define H_IMGF 800.0f
#define SCORE_T 0.05f
#define NMS_T 0.5f
#define XFORM_CLIP 4.135166556742356f

// ---------------- device scratch (zero-initialized at load) ----------------
__device__ int g_cnt[BI];
__device__ u64 g_keys[BI][CAP];          // candidates; [0,2048) reused for sorted keys
__device__ float4 g_boxes[BI][KPRE];
__device__ u32 g_clist32[BI][KPRE];      // packed: t (11b) | idx<<11 (18b)
__device__ int g_classoff[BI][CPP];
__device__ int g_classcnt[BI][CPP];
__device__ unsigned char g_keep[BI][KPRE];
__device__ int g_K[BI];
__device__ int g_done_nms[BI];

// ---------------- helpers ----------------
__device__ __forceinline__ float4 decode_clip(float4 pr, float4 rel) {
    float w = pr.z - pr.x;
    float h = pr.w - pr.y;
    float cx = pr.x + 0.5f * w;
    float cy = pr.y + 0.5f * h;
    float dx = rel.x / 10.0f;
    float dy = rel.y / 10.0f;
    float dw = fminf(rel.z / 5.0f, XFORM_CLIP);
    float dh = fminf(rel.w / 5.0f, XFORM_CLIP);
    float pcx = dx * w + cx;
    float pcy = dy * h + cy;
    float pw = expf(dw) * w;
    float ph = expf(dh) * h;
    float x1 = fminf(fmaxf(pcx - 0.5f * pw, 0.0f), W_IMGF);
    float y1 = fminf(fmaxf(pcy - 0.5f * ph, 0.0f), H_IMGF);
    float x2 = fminf(fmaxf(pcx + 0.5f * pw, 0.0f), W_IMGF);
    float y2 = fminf(fmaxf(pcy + 0.5f * ph, 0.0f), H_IMGF);
    return make_float4(x1, y1, x2, y2);
}

__device__ __forceinline__ u64 sel_mm(u64 v, u64 o, bool takeMax) {
    return takeMax ? (v > o ? v : o) : (v < o ? v : o);
}

__device__ __forceinline__ bool iou_gt(float4 bi, float ai, float4 be, float ae) {
    float lx = fmaxf(bi.x, be.x), ly = fmaxf(bi.y, be.y);
    float rx = fminf(bi.z, be.z), ry = fminf(bi.w, be.w);
    float iw = fmaxf(rx - lx, 0.f), ih = fmaxf(ry - ly, 0.f);
    float inter = iw * ih;
    float uni = ai + ae - inter;
    return inter / fmaxf(uni, 1e-9f) > NMS_T;
}

// ================= K1: softmax + candidate gen =================
__global__ void k_gen(const float* __restrict__ logits,
                      const float* __restrict__ boxreg,
                      const float* __restrict__ props) {
    int gw = (blockIdx.x * blockDim.x + threadIdx.x) >> 5;
    int lane = threadIdx.x & 31;
    if (gw >= BI * PP) return;
    int b = gw / PP;
    int p = gw - b * PP;

    const float* lrow = logits + (long long)gw * NC;
    float l0 = lrow[lane];
    float l1 = lrow[lane + 32];
    float l2 = (lane + 64 < NC) ? lrow[lane + 64] : -1e30f;

    float m = fmaxf(l0, fmaxf(l1, l2));
    #pragma unroll
    for (int o = 16; o; o >>= 1) m = fmaxf(m, __shfl_xor_sync(0xffffffffu, m, o));
    float e0 = __expf(l0 - m);
    float e1 = __expf(l1 - m);
    float e2 = (lane + 64 < NC) ? __expf(l2 - m) : 0.0f;
    float s = e0 + e1 + e2;
    #pragma unroll
    for (int o = 16; o; o >>= 1) s += __shfl_xor_sync(0xffffffffu, s, o);
    float thresh = SCORE_T * s;

    float4 pr = reinterpret_cast<const float4*>(props)[gw];

    bool ok[3];
    float sc[3];
    #pragma unroll
    for (int r = 0; r < 3; r++) {
        int ci = lane + r * 32;
        float e = (r == 0) ? e0 : ((r == 1) ? e1 : e2);
        ok[r] = false;
        sc[r] = 0.0f;
        if (ci >= 1 && ci < NC && e > thresh) {
            float4 rel = reinterpret_cast<const float4*>(boxreg)[(long long)gw * NC + ci];
            float4 bx = decode_clip(pr, rel);
            if ((bx.z - bx.x) >= 0.01f && (bx.w - bx.y) >= 0.01f) {
                ok[r] = true;
                sc[r] = e / s;
            }
        }
    }

    unsigned bal[3];
    bal[0] = __ballot_sync(0xffffffffu, ok[0]);
    bal[1] = __ballot_sync(0xffffffffu, ok[1]);
    bal[2] = __ballot_sync(0xffffffffu, ok[2]);
    int cnt0 = __popc(bal[0]);
    int cnt1 = __popc(bal[1]);
    int tot = cnt0 + cnt1 + __popc(bal[2]);
    int base = 0;
    if (lane == 0 && tot) base = atomicAdd(&g_cnt[b], tot);
    base = __shfl_sync(0xffffffffu, base, 0);

    unsigned below = (1u << lane) - 1u;
    #pragma unroll
    for (int r = 0; r < 3; r++) {
        if (ok[r]) {
            int off = __popc(bal[r] & below) + ((r > 0) ? cnt0 : 0) + ((r > 1) ? cnt1 : 0);
            int slot = base + off;
            if (slot < CAP) {
                unsigned idx = (unsigned)(p * CPP + (lane + r * 32 - 1));
                g_keys[b][slot] = ((u64)__float_as_uint(sc[r]) << 32) |
                                  (u64)(0xFFFFFFFFu - idx);
            }
        }
    }
}

// ================= K2: select top-2048, sort, class lists =================
__global__ void __launch_bounds__(1024, 1)
k_select() {
    extern __shared__ char smc[];
    u64* keys = (u64*)smc;                               // 2048 u64 (16KB)
    char* reg2 = smc + 16384;
    int* hist = (int*)reg2;                              // 8192 int (32KB)
    u64* bound = (u64*)reg2;                             // 8192 u64 (64KB)
    unsigned short* chcnt = (unsigned short*)reg2;       // 64*80 u16
    int* classoff = (int*)(reg2 + 10240);
    int* classcnt = classoff + CPP;

    __shared__ int s_t, s_A, s_R, aCtr, bCtr, wsum[32];

    const int tid = threadIdx.x;
    const int lane = tid & 31;
    const int wid = tid >> 5;
    const int b = blockIdx.x;
    const int cnt = min(g_cnt[b], CAP);
    const int K = min(cnt, KPRE);

    // A1: histogram on float bits [30:18]
    for (int i = tid; i < NBIN; i += 1024) hist[i] = 0;
    if (tid == 0) { s_t = 0x7FFFFFFF; s_A = 0; s_R = 0; aCtr = 0; bCtr = 0; }
    __syncthreads();
    for (int base = 0; base < cnt; base += 1024) {
        int i = base + tid;
        int bin = (i < cnt) ? (int)(g_keys[b][i] >> BINSHIFT) : -1;
        unsigned mask = __match_any_sync(0xffffffffu, bin);
        if (bin >= 0 && lane == (__ffs(mask) - 1))
            atomicAdd(&hist[bin], __popc(mask));
    }
    __syncthreads();

    // A2: descending scan, find rank-K crossing bin
    {
        const int BPT = NBIN / 1024;
        int localsum = 0;
        int bhi = NBIN - 1 - BPT * tid;
        #pragma unroll
        for (int j = 0; j < BPT; j++) localsum += hist[bhi - j];
        int v = localsum;
        #pragma unroll
        for (int o = 1; o < 32; o <<= 1) {
            int n = __shfl_up_sync(0xffffffffu, v, o);
            if (lane >= o) v += n;
        }
        if (lane == 31) wsum[wid] = v;
        __syncthreads();
        if (wid == 0) {
            int w = wsum[lane];
            #pragma unroll
            for (int o = 1; o < 32; o <<= 1) {
                int n = __shfl_up_sync(0xffffffffu, w, o);
                if (lane >= o) w += n;
            }
            wsum[lane] = w;
        }
        __syncthreads();
        int incl = v + ((wid > 0) ? wsum[wid - 1] : 0);
        int excl = incl - localsum;
        if (K > 0 && excl < K && K <= incl) {
            int run = excl;
            for (int j = 0; j < BPT; j++) {
                int bin = bhi - j;
                int h = hist[bin];
                if (run < K && K <= run + h) { s_t = bin; s_A = run; s_R = K - run; }
                run += h;
            }
        }
    }
    __syncthreads();
    const int tbin = s_t, A = s_A, R = s_R;
    __syncthreads();  // hist dead; bound overlays it

    // A3: compact above-bin keys; gather boundary bin
    for (int base = 0; base < cnt; base += 1024) {
        int i = base + tid;
        u64 key = (i < cnt) ? g_keys[b][i] : 0ull;
        int bin = (i < cnt) ? (int)(key >> BINSHIFT) : -1;
        bool above = bin > tbin;
        bool atb = bin == tbin;
        unsigned balA = __ballot_sync(0xffffffffu, above);
        unsigned balB = __ballot_sync(0xffffffffu, atb);
        int bA = 0, bB = 0;
        if (lane == 0) {
            if (balA) bA = atomicAdd(&aCtr, __popc(balA));
            if (balB) bB = atomicAdd(&bCtr, __popc(balB));
        }
        bA = __shfl_sync(0xffffffffu, bA, 0);
        bB = __shfl_sync(0xffffffffu, bB, 0);
        unsigned below = (1u << lane) - 1u;
        if (above) keys[bA + __popc(balA & below)] = key;
        else if (atb) {
            int pos = bB + __popc(balB & below);
            if (pos < BCAP) bound[pos] = key;
        }
    }
    __syncthreads();

    // A4: boundary bin -> top R
    int m = min(bCtr, BCAP);
    if (m > 0 && m <= 64) {
        if (wid == 0) {
            u64 r0 = (lane < m) ? bound[lane] : 0ull;
            u64 r1 = (lane + 32 < m) ? bound[lane + 32] : 0ull;
            #pragma unroll
            for (int k2 = 2; k2 <= 32; k2 <<= 1) {
                #pragma unroll
                for (int j = k2 >> 1; j; j >>= 1) {
                    {
                        u64 o = __shfl_xor_sync(0xffffffffu, r0, j);
                        r0 = sel_mm(r0, o, ((lane & k2) == 0) == ((lane & j) == 0));
                    }
                    {
                        int x = lane + 32;
                        u64 o = __shfl_xor_sync(0xffffffffu, r1, j);
                        r1 = sel_mm(r1, o, ((x & k2) == 0) == ((x & j) == 0));
                    }
                }
            }
            u64 hi = (r0 > r1) ? r0 : r1;
            u64 lo = (r0 > r1) ? r1 : r0;
            r0 = hi; r1 = lo;
            #pragma unroll
            for (int j = 16; j; j >>= 1) {
                bool tkm = ((lane & j) == 0);
                u64 o0 = __shfl_xor_sync(0xffffffffu, r0, j);
                u64 o1 = __shfl_xor_sync(0xffffffffu, r1, j);
                r0 = sel_mm(r0, o0, tkm);
                r1 = sel_mm(r1, o1, tkm);
            }
            if (lane < R) keys[A + lane] = r0;
            if (lane + 32 < R) keys[A + lane + 32] = r1;
        }
    } else if (m > 64) {
        int M = 1;
        while (M < m) M <<= 1;
        for (int i = m + tid; i < M; i += 1024) bound[i] = 0ull;
        __syncthreads();
        for (int k2 = 2; k2 <= M; k2 <<= 1) {
            for (int j = k2 >> 1; j; j >>= 1) {
                for (int i = tid; i < M; i += 1024) {
                    int ixj = i ^ j;
                    if (ixj > i) {
                        u64 a = bound[i], c = bound[ixj];
                        bool up = ((i & k2) == 0);
                        if ((a < c) == up) { bound[i] = c; bound[ixj] = a; }
                    }
                }
                __syncthreads();
            }
        }
        for (int i = tid; i < R; i += 1024) keys[A + i] = bound[i];
    }
    for (int i = K + tid; i < KPRE; i += 1024) keys[i] = 0ull;
    __syncthreads();

    // A5: descending bitonic sort (register 64-blocks + smem merges)
    {
        int base = wid * 64;
        u64 r0 = keys[base + lane];
        u64 r1 = keys[base + lane + 32];
        #pragma unroll
        for (int k2 = 2; k2 <= 32; k2 <<= 1) {
            #pragma unroll
            for (int j = k2 >> 1; j; j >>= 1) {
                {
                    int x = lane;
                    u64 o = __shfl_xor_sync(0xffffffffu, r0, j);
                    r0 = sel_mm(r0, o, ((x & k2) == 0) == ((x & j) == 0));
                }
                {
                    int x = lane + 32;
                    u64 o = __shfl_xor_sync(0xffffffffu, r1, j);
                    r1 = sel_mm(r1, o, ((x & k2) == 0) == ((x & j) == 0));
                }
            }
        }
        {
            bool up = ((wid & 1) == 0);
            u64 lo = (r0 < r1) ? r0 : r1;
            u64 hi = (r0 < r1) ? r1 : r0;
            r0 = up ? hi : lo;
            r1 = up ? lo : hi;
            #pragma unroll
            for (int j = 16; j; j >>= 1) {
                bool tkm = up == ((lane & j) == 0);
                u64 o0 = __shfl_xor_sync(0xffffffffu, r0, j);
                u64 o1 = __shfl_xor_sync(0xffffffffu, r1, j);
                r0 = sel_mm(r0, o0, tkm);
                r1 = sel_mm(r1, o1, tkm);
            }
        }
        keys[base + lane] = r0;
        keys[base + lane + 32] = r1;
    }
    __syncthreads();
    for (int k2 = 128; k2 <= KPRE; k2 <<= 1) {
        for (int j = k2 >> 1; j >= 64; j >>= 1) {
            int i = ((tid & ~(j - 1)) << 1) | (tid & (j - 1));
            u64 a = keys[i], c = keys[i + j];
            bool up = ((i & k2) == 0);
            if ((a < c) == up) { keys[i] = c; keys[i + j] = a; }
            __syncthreads();
        }
        {
            int base = wid * 64;
            bool up = ((base & k2) == 0);
            u64 r0 = keys[base + lane];
            u64 r1 = keys[base + lane + 32];
            u64 lo = (r0 < r1) ? r0 : r1;
            u64 hi = (r0 < r1) ? r1 : r0;
            r0 = up ? hi : lo;
            r1 = up ? lo : hi;
            #pragma unroll
            for (int j = 16; j; j >>= 1) {
                bool tkm = up == ((lane & j) == 0);
                u64 o0 = __shfl_xor_sync(0xffffffffu, r0, j);
                u64 o1 = __shfl_xor_sync(0xffffffffu, r1, j);
                r0 = sel_mm(r0, o0, tkm);
                r1 = sel_mm(r1, o1, tkm);
            }
            keys[base + lane] = r0;
            keys[base + lane + 32] = r1;
        }
        __syncthreads();
    }

    // B1: store sorted keys
    for (int t = tid; t < KPRE; t += 1024) g_keys[b][t] = keys[t];
    for (int i = tid; i < 64 * CPP; i += 1024) chcnt[i] = 0;
    __syncthreads();

    // B2: stable counting sort by class -> g_clist32 (packed t|idx<<11)
    for (int c = wid; c < 64; c += 32) {
        int t = c * 32 + lane;
        u64 key = keys[t];
        u32 low = 0xFFFFFFFFu - (u32)key;
        unsigned L = (t < K) ? (low % CPP) : 0xFFu;
        unsigned mask = __match_any_sync(0xffffffffu, L);
        if (L < CPP && lane == (__ffs(mask) - 1))
            chcnt[c * CPP + L] = (unsigned short)__popc(mask);
    }
    __syncthreads();
    if (tid < CPP) {
        int run = 0;
        for (int c = 0; c < 64; c++) {
            int v = chcnt[c * CPP + tid];
            chcnt[c * CPP + tid] = (unsigned short)run;
            run += v;
        }
        classcnt[tid] = run;
        g_classcnt[b][tid] = run;
    }
    __syncthreads();
    {
        int v = 0;
        if (tid < 96) {
            v = (tid < CPP) ? classcnt[tid] : 0;
            #pragma unroll
            for (int o = 1; o < 32; o <<= 1) {
                int n = __shfl_up_sync(0xffffffffu, v, o);
                if (lane >= o) v += n;
            }
            if (lane == 31) wsum[wid] = v;
        }
        __syncthreads();
        if (tid < CPP) {
            int add = 0;
            for (int w = 0; w < wid; w++) add += wsum[w];
            int off = v + add - classcnt[tid];
            classoff[tid] = off;
            g_classoff[b][tid] = off;
        }
    }
    __syncthreads();
    for (int c = wid; c < 64; c += 32) {
        int t = c * 32 + lane;
        u64 key = keys[t];
        u32 low = 0xFFFFFFFFu - (u32)key;
        unsigned L = (t < K) ? (low % CPP) : 0xFFu;
        unsigned mask = __match_any_sync(0xffffffffu, L);
        if (L < CPP) {
            int rank = __popc(mask & ((1u << lane) - 1u));
            g_clist32[b][classoff[L] + chcnt[c * CPP + L] + rank] =
                (u32)t | (low << 11);
        }
    }

    if (tid == 0) { g_K[b] = K; g_cnt[b] = 0; }
}

// ================= K3: mask-parallel NMS + fused output =================
__global__ void __launch_bounds__(128)
k_nms_out(const float* __restrict__ boxreg,
          const float* __restrict__ props,
          float* __restrict__ out) {
    __shared__ float4 sbox[MAXN];
    __shared__ float sarea[MAXN];
    __shared__ unsigned short slist[MAXN];
    __shared__ u64 smask[MAXN * 4];      // mask rows, NW<=4 words each
    __shared__ u64 skept[4];
    __shared__ int sdone, sKeptTot, wscan[4];

    const int cls = blockIdx.x;
    const int b = blockIdx.y;
    const int tid = threadIdx.x;
    const int lane = tid & 31;
    const int wid = tid >> 5;
    const int n = g_classcnt[b][cls];

    if (n > 0) {
        const int off = g_classoff[b][cls];
        // decode this class's boxes (parallel)
        for (int e = tid; e < n; e += 128) {
            u32 rec = g_clist32[b][off + e];
            int t = rec & 0x7FF;
            u32 idx = rec >> 11;
            int p = idx / CPP;
            int cm1 = idx - p * CPP;
            int gw = b * PP + p;
            float4 pr = reinterpret_cast<const float4*>(props)[gw];
            float4 rel = reinterpret_cast<const float4*>(boxreg)[(long long)gw * NC + cm1 + 1];
            float4 bx = decode_clip(pr, rel);
            g_boxes[b][t] = bx;
            if (e < MAXN) {
                sbox[e] = bx;
                sarea[e] = fmaxf(bx.z - bx.x, 0.f) * fmaxf(bx.w - bx.y, 0.f);
                slist[e] = (unsigned short)t;
            }
        }
        __syncthreads();

        if (n <= MAXN) {
            // ---- fast path: parallel mask build + short serial reduce ----
            const int NW = (n + 63) >> 6;
            for (int i = wid; i < n; i += 4) {
                float4 bi = sbox[i];
                float ai = sarea[i];
                for (int w = 0; w < NW; w++) {
                    int j0 = w * 64 + lane;
                    int j1 = j0 + 32;
                    bool s0 = (j0 > i && j0 < n) && iou_gt(bi, ai, sbox[j0], sarea[j0]);
                    bool s1 = (j1 > i && j1 < n) && iou_gt(bi, ai, sbox[j1], sarea[j1]);
                    unsigned m0 = __ballot_sync(0xffffffffu, s0);
                    unsigned m1 = __ballot_sync(0xffffffffu, s1);
                    if (lane == 0) smask[i * NW + w] = (u64)m0 | ((u64)m1 << 32);
                }
            }
            __syncthreads();
            if (tid == 0) {
                if (NW == 1) {
                    u64 kept = ~0ull;
                    for (int i = 0; i < n; i++)
                        if ((kept >> i) & 1ull) kept &= ~smask[i];
                    skept[0] = kept; skept[1] = 0; skept[2] = 0; skept[3] = 0;
                } else {
                    u64 k0 = ~0ull, k1 = ~0ull, k2 = ~0ull, k3 = ~0ull;
                    for (int i = 0; i < n; i++) {
                        int w = i >> 6;
                        u64 kw = (w == 0) ? k0 : ((w == 1) ? k1 : ((w == 2) ? k2 : k3));
                        if ((kw >> (i & 63)) & 1ull) {
                            const u64* row = &smask[i * NW];
                            k0 &= ~row[0];
                            if (NW > 1) k1 &= ~row[1];
                            if (NW > 2) k2 &= ~row[2];
                            if (NW > 3) k3 &= ~row[3];
                        }
                    }
                    skept[0] = k0; skept[1] = k1; skept[2] = k2; skept[3] = k3;
                }
            }
            __syncthreads();
            for (int e = tid; e < n; e += 128)
                g_keep[b][slist[e]] = (unsigned char)((skept[e >> 6] >> (e & 63)) & 1ull);
        } else if (wid == 0) {
            // ---- fallback (n > MAXN, practically never): old warp-serial ----
            u64 kept = ~0ull;  // bit ss over groups of 32
            for (int i = 0; i < n; i++) {
                int il = i & 31, is = i >> 5;
                unsigned ki = __shfl_sync(0xffffffffu, (unsigned)((kept >> is) & 1ull), il);
                if (!ki) continue;
                float4 bi;
                float ai;
                if (i < MAXN) { bi = sbox[i]; ai = sarea[i]; }
                else {
                    u32 rec = g_clist32[b][off + i];
                    bi = g_boxes[b][rec & 0x7FF];
                    ai = fmaxf(bi.z - bi.x, 0.f) * fmaxf(bi.w - bi.y, 0.f);
                }
                for (int ss = is; ss * 32 + lane < n && ss < 64; ss++) {
                    int e = ss * 32 + lane;
                    if (e > i && ((kept >> ss) & 1ull)) {
                        float4 be;
                        float ae;
                        if (e < MAXN) { be = sbox[e]; ae = sarea[e]; }
                        else {
                            u32 rec = g_clist32[b][off + e];
                            be = g_boxes[b][rec & 0x7FF];
                            ae = fmaxf(be.z - be.x, 0.f) * fmaxf(be.w - be.y, 0.f);
                        }
                        if (iou_gt(bi, ai, be, ae)) kept &= ~(1ull << ss);
                    }
                }
            }
            for (int ss = 0; ss * 32 + lane < n && ss < 64; ss++) {
                int e = ss * 32 + lane;
                u32 rec = g_clist32[b][off + e];
                g_keep[b][rec & 0x7FF] = (unsigned char)((kept >> ss) & 1ull);
            }
        }
    }

    // ---- last-block-done: 80th block for image b emits output ----
    __threadfence();
    __syncthreads();
    if (tid == 0) sdone = atomicAdd(&g_done_nms[b], 1);
    __syncthreads();
    if (sdone != CPP - 1) return;
    __threadfence();

    // stable compaction: kept (t asc) then non-kept (t asc); top-100 out.
    const int CH = KPRE / 128;  // 16 entries per thread
    int base = tid * CH;
    u64 f0 = *reinterpret_cast<const u64*>(&g_keep[b][base]);
    u64 f1 = *reinterpret_cast<const u64*>(&g_keep[b][base + 8]);
    int cnts = __popcll(f0 & 0x0101010101010101ull) +
               __popcll(f1 & 0x0101010101010101ull);
    int v = cnts;
    #pragma unroll
    for (int o = 1; o < 32; o <<= 1) {
        int t2 = __shfl_up_sync(0xffffffffu, v, o);
        if (lane >= o) v += t2;
    }
    if (lane == 31) wscan[wid] = v;
    __syncthreads();
    if (tid == 0) {
        int run = 0;
        #pragma unroll
        for (int w = 0; w < 4; w++) { int t2 = wscan[w]; wscan[w] = run; run += t2; }
        sKeptTot = run;
    }
    __syncthreads();
    int run = (v - cnts) + wscan[wid];
    int keptTotal = sKeptTot;
    #pragma unroll
    for (int j = 0; j < CH; j++) {
        int e = base + j;
        bool kp = (((j < 8) ? (f0 >> (8 * j)) : (f1 >> (8 * (j - 8)))) & 1ull) != 0;
        int slot;
        if (kp) { slot = run; run++; }
        else slot = keptTotal + (e - run);
        if (slot < DET) {
            u64 key = g_keys[b][e];
            float sc = kp ? __uint_as_float((u32)(key >> 32)) : -1.0f;
            u32 idx = 0xFFFFFFFFu - (u32)key;
            float4 bx = g_boxes[b][e];
            out[(b * DET + slot) * 4 + 0] = bx.x;
            out[(b * DET + slot) * 4 + 1] = bx.y;
            out[(b * DET + slot) * 4 + 2] = bx.z;
            out[(b * DET + slot) * 4 + 3] = bx.w;
            out[BI * DET * 4 + b * DET + slot] = sc;
            out[BI * DET * 5 + b * DET + slot] = (float)(idx % CPP + 1);
            out[BI * DET * 6 + b * DET + slot] = kp ? 1.0f : 0.0f;
        }
    }
    if (tid == 0) g_done_nms[b] = 0;  // reset for next replay
}

// ---------------- launch ----------------
extern "C" void kernel_launch(void* const* d_in, const int* in_sizes, int n_in,
                              void* d_out, int out_size) {
    const float* logits = (const float*)d_in[0];
    const float* boxreg = (const float*)d_in[1];
    const float* props  = (const float*)d_in[2];
    float* out = (float*)d_out;

    cudaFuncSetAttribute(k_select, cudaFuncAttributeMaxDynamicSharedMemorySize, 81920);

    k_gen<<<(BI * PP * 32 + 255) / 256, 256>>>(logits, boxreg, props);
    k_select<<<BI, 1024, 81920>>>();
    k_nms_out<<<dim3(CPP, BI), 128>>>(boxreg, props, out);
}